// round 13
// baseline (speedup 1.0000x reference)
#include <cuda_runtime.h>

// QuantumFeatureExtractor — analytic collapse, vectorized fp32 path.
// TERMINAL / FROZEN. This exact binary passed R6/R8/R11 at 4.61/4.70/4.86us
// (kernel-dur 3.68/4.00/4.51) — the graph-replay launch floor's noise band.
// R12's container failure on the identical binary = infra flake, resubmitted.
// ncu: DRAM 0%, L2 0.3%, all pipes 0%, 16 regs; executed work ~0.2-0.3us of
// the ~4us measured. Nothing left to optimize.
//
// Math: the circuit applies one RX(x[b,i]+theta[i]) per distinct qubit to
// |0..0>, so the state remains a product state and <Z_i> = cos(x[b,i]+theta[i]).
// The reference's 16 x 2^20 complex statevector simulation collapses to 320
// cosines.
//
// Frozen lessons (do not revisit):
//  - fp64 cos: +1us on the weak FP64 pipe (R1) — use MUFU __cosf
//    (|angle| < ~7, abs err ~1e-6 vs 1e-3 rel budget; rel_err 2.3e-7).
//  - vector load of theta (d_in[1], 80B tensor): R4/R5 failures coincided
//    with it (possibly infra, but upside <0.1us = below noise) — stay scalar.
//  - folding tail work into fewer warps lengthens the slowest warp's serial
//    dependent path, +1us (R7) — one float4 per thread, 3 warps.
//  - index-math / block-shape micro-trims (float2x160t, 2D (5,16) block):
//    all within the +/-0.25us noise band (R9/R10).

#define BATCH 16
#define N_QUBITS 20
#define TOTAL (BATCH * N_QUBITS)   // 320
#define NTHREADS (TOTAL / 4)       // 80 threads = 3 warps

__global__ __launch_bounds__(NTHREADS, 1)
void qfe_kernel(const float4* __restrict__ x4,
                const float* __restrict__ theta,
                float4* __restrict__ out4) {
    int t = threadIdx.x;           // 0..79
    float4 v = x4[t];
    // element base = 4t; q0 = (4t) % 20 is a multiple of 4 in [0,16],
    // so the 4 thetas for this thread are theta[q0..q0+3], no wraparound.
    int q0 = (t % (N_QUBITS / 4)) * 4;   // (t % 5) * 4
    float4 r;
    r.x = __cosf(v.x + theta[q0 + 0]);
    r.y = __cosf(v.y + theta[q0 + 1]);
    r.z = __cosf(v.z + theta[q0 + 2]);
    r.w = __cosf(v.w + theta[q0 + 3]);
    out4[t] = r;
}

extern "C" void kernel_launch(void* const* d_in, const int* in_sizes, int n_in,
                              void* d_out, int out_size) {
    const float4* x4   = (const float4*)d_in[0];  // [16,20] fp32, 320 elems
    const float* theta = (const float*)d_in[1];   // [20] fp32
    float4* out4 = (float4*)d_out;                // [16,20] fp32
    qfe_kernel<<<1, NTHREADS>>>(x4, theta, out4);
}

// round 14
// speedup vs baseline: 1.0065x; 1.0065x over previous
#include <cuda_runtime.h>

// QuantumFeatureExtractor — analytic collapse, vectorized fp32 path.
// TERMINAL / FROZEN. This exact binary benched 4.61/4.70/4.86/4.99us across
// four runs (kernel-dur 3.68/4.00/4.51/4.19) — i.i.d. draws from the
// graph-replay launch-floor noise distribution (~4.8 +/- 0.2us). ncu is
// invariant across runs: DRAM 0%, L2 ~0.3%, all pipes 0%, 16 regs, 3 warps.
// Executed work is ~0.2-0.3us of the measured time; the kernel is
// launch-overhead bound and no configuration change can move it.
//
// Math: the circuit applies one RX(x[b,i]+theta[i]) per distinct qubit to
// |0..0>, so the state remains a product state and <Z_i> = cos(x[b,i]+theta[i]).
// The reference's 16 x 2^20 complex statevector simulation collapses to 320
// cosines.
//
// Frozen lessons (do not revisit):
//  - fp64 cos: +1us on the weak FP64 pipe (R1) — use MUFU __cosf
//    (|angle| < ~7, abs err ~1e-6 vs 1e-3 rel budget; rel_err 2.3e-7).
//  - vector load of theta (d_in[1], 80B tensor): R4/R5 container kills
//    coincided with it; upside <0.1us (below noise) — stay scalar.
//  - folding work into fewer warps lengthens the slowest warp's serial
//    dependent path, +1us (R7) — one float4 per thread, 3 warps.
//  - __constant__ staging of theta would add a graph node — worse.
//  - index-math / block-shape micro-trims (float2x160t, 2D (5,16) block):
//    all within the noise band (R9/R10).

#define BATCH 16
#define N_QUBITS 20
#define TOTAL (BATCH * N_QUBITS)   // 320
#define NTHREADS (TOTAL / 4)       // 80 threads = 3 warps

__global__ __launch_bounds__(NTHREADS, 1)
void qfe_kernel(const float4* __restrict__ x4,
                const float* __restrict__ theta,
                float4* __restrict__ out4) {
    int t = threadIdx.x;           // 0..79
    float4 v = x4[t];
    // element base = 4t; q0 = (4t) % 20 is a multiple of 4 in [0,16],
    // so the 4 thetas for this thread are theta[q0..q0+3], no wraparound.
    int q0 = (t % (N_QUBITS / 4)) * 4;   // (t % 5) * 4
    float4 r;
    r.x = __cosf(v.x + theta[q0 + 0]);
    r.y = __cosf(v.y + theta[q0 + 1]);
    r.z = __cosf(v.z + theta[q0 + 2]);
    r.w = __cosf(v.w + theta[q0 + 3]);
    out4[t] = r;
}

extern "C" void kernel_launch(void* const* d_in, const int* in_sizes, int n_in,
                              void* d_out, int out_size) {
    const float4* x4   = (const float4*)d_in[0];  // [16,20] fp32, 320 elems
    const float* theta = (const float*)d_in[1];   // [20] fp32
    float4* out4 = (float4*)d_out;                // [16,20] fp32
    qfe_kernel<<<1, NTHREADS>>>(x4, theta, out4);
}

// round 15
// speedup vs baseline: 1.0263x; 1.0197x over previous
#include <cuda_runtime.h>

// QuantumFeatureExtractor — analytic collapse, vectorized fp32 path.
// TERMINAL / FROZEN. This exact binary benched 4.61/4.70/4.86/4.99/4.96us
// across five runs (kernel-dur 3.68/4.00/4.51/4.19/3.94) — i.i.d. draws from
// the graph-replay launch-floor noise distribution (~4.8 +/- 0.17us). Bench
// dur and ncu kernel-dur are decorrelated across runs, proving the variance
// lives in measurement/replay, not in the kernel. ncu invariant: DRAM 0%,
// L2 ~0.3%, all pipes 0%, 16 regs, 3 warps. Executed work ~0.2-0.3us.
//
// Math: the circuit applies one RX(x[b,i]+theta[i]) per distinct qubit to
// |0..0>, so the state remains a product state and <Z_i> = cos(x[b,i]+theta[i]).
// The reference's 16 x 2^20 complex statevector simulation collapses to 320
// cosines.
//
// Frozen lessons (do not revisit):
//  - fp64 cos: +1us on the weak FP64 pipe (R1) — use MUFU __cosf
//    (|angle| < ~7, abs err ~1e-6 vs 1e-3 rel budget; rel_err 2.3e-7).
//  - vector load of theta (d_in[1], 80B tensor): R4/R5 container kills
//    coincided with it; upside <0.1us (below noise) — stay scalar.
//  - folding work into fewer warps lengthens the slowest warp's serial
//    dependent path, +1us (R7) — one float4 per thread, 3 warps.
//  - __constant__ staging of theta would add a graph node — worse.
//  - index-math / block-shape micro-trims (float2x160t, 2D (5,16) block):
//    all within the noise band (R9/R10).

#define BATCH 16
#define N_QUBITS 20
#define TOTAL (BATCH * N_QUBITS)   // 320
#define NTHREADS (TOTAL / 4)       // 80 threads = 3 warps

__global__ __launch_bounds__(NTHREADS, 1)
void qfe_kernel(const float4* __restrict__ x4,
                const float* __restrict__ theta,
                float4* __restrict__ out4) {
    int t = threadIdx.x;           // 0..79
    float4 v = x4[t];
    // element base = 4t; q0 = (4t) % 20 is a multiple of 4 in [0,16],
    // so the 4 thetas for this thread are theta[q0..q0+3], no wraparound.
    int q0 = (t % (N_QUBITS / 4)) * 4;   // (t % 5) * 4
    float4 r;
    r.x = __cosf(v.x + theta[q0 + 0]);
    r.y = __cosf(v.y + theta[q0 + 1]);
    r.z = __cosf(v.z + theta[q0 + 2]);
    r.w = __cosf(v.w + theta[q0 + 3]);
    out4[t] = r;
}

extern "C" void kernel_launch(void* const* d_in, const int* in_sizes, int n_in,
                              void* d_out, int out_size) {
    const float4* x4   = (const float4*)d_in[0];  // [16,20] fp32, 320 elems
    const float* theta = (const float*)d_in[1];   // [20] fp32
    float4* out4 = (float4*)d_out;                // [16,20] fp32
    qfe_kernel<<<1, NTHREADS>>>(x4, theta, out4);
}

// round 16
// speedup vs baseline: 1.0612x; 1.0340x over previous
#include <cuda_runtime.h>

// QuantumFeatureExtractor — analytic collapse, vectorized fp32 path.
// TERMINAL / FROZEN (R6 configuration). Six bench samples of this exact
// binary: 4.61/4.70/4.86/4.99/4.96/4.86us (mean 4.83 +/- 0.14); ncu
// kernel-dur 3.68-4.51us, decorrelated from bench dur — variance lives in
// graph-replay measurement, not the kernel. ncu invariant across all runs:
// DRAM 0%, L2 ~0.3%, all pipes 0%, 16 regs, 3 warps, ~15 SASS instructions.
// Executed work ~0.2-0.3us of the ~4us floor. No lever above noise remains.
//
// Math: the circuit applies one RX(x[b,i]+theta[i]) per distinct qubit to
// |0..0>, so the state remains a product state and
//   <Z_i> = cos^2(phi/2) - sin^2(phi/2) = cos(x[b,i] + theta[i]).
// The reference's 16 x 2^20 complex statevector simulation (20 sweeps,
// ~128MB of state) collapses to 320 cosines.
//
// Frozen lessons (do not revisit):
//  - fp64 cos: +1us on the weak FP64 pipe (R1) — use MUFU __cosf
//    (|angle| < ~7, abs err ~1e-6 vs 1e-3 rel budget; rel_err 2.3e-7).
//  - vector load of theta (d_in[1], 80B tensor): R4/R5 container kills
//    coincided with it; upside <0.1us (below noise) — stay scalar.
//  - folding work into fewer warps lengthens the slowest warp's serial
//    dependent path, +1us (R7) — one float4 per thread, 3 warps.
//  - __constant__ staging of theta would add a graph node — worse.
//  - index-math / block-shape micro-trims (float2x160t, 2D (5,16) block):
//    all within the noise band (R9/R10).

#define BATCH 16
#define N_QUBITS 20
#define TOTAL (BATCH * N_QUBITS)   // 320
#define NTHREADS (TOTAL / 4)       // 80 threads = 3 warps

__global__ __launch_bounds__(NTHREADS, 1)
void qfe_kernel(const float4* __restrict__ x4,
                const float* __restrict__ theta,
                float4* __restrict__ out4) {
    int t = threadIdx.x;           // 0..79
    float4 v = x4[t];
    // element base = 4t; q0 = (4t) % 20 is a multiple of 4 in [0,16],
    // so the 4 thetas for this thread are theta[q0..q0+3], no wraparound.
    int q0 = (t % (N_QUBITS / 4)) * 4;   // (t % 5) * 4
    float4 r;
    r.x = __cosf(v.x + theta[q0 + 0]);
    r.y = __cosf(v.y + theta[q0 + 1]);
    r.z = __cosf(v.z + theta[q0 + 2]);
    r.w = __cosf(v.w + theta[q0 + 3]);
    out4[t] = r;
}

extern "C" void kernel_launch(void* const* d_in, const int* in_sizes, int n_in,
                              void* d_out, int out_size) {
    const float4* x4   = (const float4*)d_in[0];  // [16,20] fp32, 320 elems
    const float* theta = (const float*)d_in[1];   // [20] fp32
    float4* out4 = (float4*)d_out;                // [16,20] fp32
    qfe_kernel<<<1, NTHREADS>>>(x4, theta, out4);
}